// round 8
// baseline (speedup 1.0000x reference)
#include <cuda_runtime.h>
#include <cuda.h>
#include <cuda_bf16.h>
#include <stdint.h>

#define DI __device__ __forceinline__

// ---------------- problem constants ----------------
static constexpr int    NDIM     = 4096;
static constexpr float  INVSCALE = 1.0f / (31.75f * 127.0f);   // 1/(sx*sw)

// ---------------- GEMM tiling (bf16 HMMA + TMA, warp-specialized) ----------------
static constexpr int BM = 128, BN = 128, BK = 64;
static constexpr int STAGES = 3;
static constexpr int KT = NDIM / BK;                    // 64 k-iterations
static constexpr int A_STAGE_B = BM * 128;              // 16384 (128 rows x 128B)
static constexpr int B_STAGE_B = BN * 128;              // 16384
static constexpr int STAGE_B   = A_STAGE_B + B_STAGE_B; // 32768
static constexpr int SMEM_HDR  = 1024;
static constexpr int SMEM_TOTAL = SMEM_HDR + STAGES * STAGE_B;  // 99328
static constexpr int NCONS = 256;                       // consumer threads

// ---------------- device scratch (allocation-free rule) ----------------
__device__ __nv_bfloat16 g_Xq[(size_t)NDIM * NDIM];   // quantized activations (integer-valued bf16)
__device__ __nv_bfloat16 g_Wq[(size_t)NDIM * NDIM];   // quantized weights (integer-valued bf16)
__device__ float         g_badd[NDIM];                // epilogue bias term

// ---------------- PTX helpers ----------------
DI uint32_t smem_u32(const void* p) {
    uint32_t a;
    asm("{ .reg .u64 t; cvta.to.shared.u64 t, %1; cvt.u32.u64 %0, t; }" : "=r"(a) : "l"(p));
    return a;
}
DI void ldsm4(uint32_t* r, uint32_t addr) {
    asm volatile("ldmatrix.sync.aligned.m8n8.x4.shared.b16 {%0,%1,%2,%3}, [%4];"
                 : "=r"(r[0]), "=r"(r[1]), "=r"(r[2]), "=r"(r[3]) : "r"(addr));
}
DI void mma16816(float* c, const uint32_t* a, uint32_t b0, uint32_t b1) {
    asm volatile(
        "mma.sync.aligned.m16n8k16.row.col.f32.bf16.bf16.f32 "
        "{%0,%1,%2,%3}, {%4,%5,%6,%7}, {%8,%9}, {%0,%1,%2,%3};"
        : "+f"(c[0]), "+f"(c[1]), "+f"(c[2]), "+f"(c[3])
        : "r"(a[0]), "r"(a[1]), "r"(a[2]), "r"(a[3]), "r"(b0), "r"(b1));
}
// SW128 swizzled byte offset: 128B rows, 16B chunk c in [0,8)
DI uint32_t sw_off(int row, int c) {
    return (uint32_t)(row * 128 + ((c ^ (row & 7)) << 4));
}
DI void mbar_init(uint32_t a, uint32_t cnt) {
    asm volatile("mbarrier.init.shared.b64 [%0], %1;" :: "r"(a), "r"(cnt) : "memory");
}
DI void mbar_expect(uint32_t a, uint32_t bytes) {
    asm volatile("mbarrier.arrive.expect_tx.shared.b64 _, [%0], %1;"
                 :: "r"(a), "r"(bytes) : "memory");
}
DI void mbar_arrive(uint32_t a) {
    asm volatile("mbarrier.arrive.shared.b64 _, [%0];" :: "r"(a) : "memory");
}
DI void mbar_wait(uint32_t a, uint32_t parity) {
    asm volatile(
        "{\n\t.reg .pred P;\n"
        "WL_%=:\n\t"
        "mbarrier.try_wait.parity.acquire.cta.shared::cta.b64 P, [%0], %1, 0x989680;\n\t"
        "@P bra WD_%=;\n\t"
        "bra WL_%=;\n"
        "WD_%=:\n\t}"
        :: "r"(a), "r"(parity) : "memory");
}
DI void tma2d(uint32_t dst, const CUtensorMap* tm, int cx, int cy, uint32_t mbar) {
    asm volatile(
        "cp.async.bulk.tensor.2d.shared::cluster.global.tile.mbarrier::complete_tx::bytes "
        "[%0], [%1, {%2, %3}], [%4];"
        :: "r"(dst), "l"(tm), "r"(cx), "r"(cy), "r"(mbar) : "memory");
}

// ---------------- quantize kernels ----------------
__global__ void quant_kernel(const float4* __restrict__ src, int which,
                             float clip, float scale) {
    size_t i = (size_t)blockIdx.x * blockDim.x + threadIdx.x;
    float4 v = src[i];
    float a0 = rintf(fminf(clip, fmaxf(-clip, v.x)) * scale);
    float a1 = rintf(fminf(clip, fmaxf(-clip, v.y)) * scale);
    float a2 = rintf(fminf(clip, fmaxf(-clip, v.z)) * scale);
    float a3 = rintf(fminf(clip, fmaxf(-clip, v.w)) * scale);
    __nv_bfloat162 p0 = __floats2bfloat162_rn(a0, a1);
    __nv_bfloat162 p1 = __floats2bfloat162_rn(a2, a3);
    uint2 o;
    o.x = *reinterpret_cast<uint32_t*>(&p0);
    o.y = *reinterpret_cast<uint32_t*>(&p1);
    uint2* dst = reinterpret_cast<uint2*>(which ? g_Wq : g_Xq);
    dst[i] = o;
}

__global__ void quant_bias_kernel(const float* __restrict__ b) {
    int i = blockIdx.x * blockDim.x + threadIdx.x;
    float q = rintf(fminf(1.0f, fmaxf(-1.0f, b[i])) * 127.0f);
    g_badd[i] = 32.0f * q * INVSCALE;   // quantized ones-column (=32) * quantized bias
}

// ---------------- GEMM: producer warp (TMA) + 8 consumer warps (HMMA) ----------------
__global__ __launch_bounds__(288, 2)
void gemm_kernel(const __grid_constant__ CUtensorMap tmA,
                 const __grid_constant__ CUtensorMap tmB,
                 const float* __restrict__ noise, float* __restrict__ out) {
    extern __shared__ __align__(1024) char smem[];
    const uint32_t sb = smem_u32(smem);
    const int tid  = threadIdx.x;
    const int lane = tid & 31;

    const uint32_t FULL  = sb;       // full[s]  at sb + 8*s
    const uint32_t EMPTY = sb + 24;  // empty[s] at sb + 24 + 8*s

    if (tid == 0) {
#pragma unroll
        for (int s = 0; s < STAGES; ++s) {
            mbar_init(FULL + 8u * s, 1);
            mbar_init(EMPTY + 8u * s, NCONS);
        }
        asm volatile("fence.mbarrier_init.release.cluster;" ::: "memory");
    }
    __syncthreads();

    const int tileM = blockIdx.y, tileN = blockIdx.x;

    if (tid >= NCONS) {
        // ================= producer warp (lane 0 only) =================
        if (lane == 0) {
#pragma unroll
            for (int f = 0; f < STAGES; ++f) {
                const uint32_t a_s = sb + SMEM_HDR + f * STAGE_B;
                mbar_expect(FULL + 8u * f, (uint32_t)STAGE_B);
                tma2d(a_s,             &tmA, f * BK, tileM * BM, FULL + 8u * f);
                tma2d(a_s + A_STAGE_B, &tmB, f * BK, tileN * BN, FULL + 8u * f);
            }
            int s = 0, php = 0;
            for (int f = STAGES; f < KT; ++f) {
                const uint32_t a_s = sb + SMEM_HDR + s * STAGE_B;
                mbar_wait(EMPTY + 8u * s, (uint32_t)php);
                mbar_expect(FULL + 8u * s, (uint32_t)STAGE_B);
                tma2d(a_s,             &tmA, f * BK, tileM * BM, FULL + 8u * s);
                tma2d(a_s + A_STAGE_B, &tmB, f * BK, tileN * BN, FULL + 8u * s);
                if (++s == STAGES) { s = 0; php ^= 1; }
            }
        }
        return;
    }

    // ================= consumer warps =================
    const int warp  = tid >> 5;
    const int warpM = warp >> 1;     // 0..3, 32 rows each
    const int warpN = warp & 1;      // 0..1, 64 cols each

    float c[2][8][4];
#pragma unroll
    for (int i = 0; i < 2; ++i)
#pragma unroll
        for (int j = 0; j < 8; ++j)
#pragma unroll
            for (int k = 0; k < 4; ++k) c[i][j][k] = 0.0f;

    // per-lane swizzled ldmatrix base offsets (swizzle invariant under row+16 => +2048B)
    const int lrow = lane & 15;
    const int csel = lane >> 4;
    uint32_t offA0[4], offB0[4];
    {
        const int rA = warpM * 32 + lrow;
        const int rB = warpN * 64 + lrow;
#pragma unroll
        for (int kk = 0; kk < 4; ++kk) {
            offA0[kk] = sw_off(rA, (kk << 1) | csel);
            offB0[kk] = sw_off(rB, (kk << 1) | csel);
        }
    }

    // double-buffered fragments: a by kk parity, b by (kk*4+q) parity
    uint32_t afr[2][2][4];   // [parity][m-half][reg]
    uint32_t bfr[2][4];      // [parity][reg]

    int s = 0, ph = 0;
    uint32_t a_s = sb + SMEM_HDR;             // stage 0

    // bootstrap: stage 0 kk0 fragments
    mbar_wait(FULL + 0u, 0u);
    ldsm4(afr[0][0], a_s + offA0[0]);
    ldsm4(afr[0][1], a_s + offA0[0] + 2048);
    ldsm4(bfr[0], a_s + A_STAGE_B + offB0[0]);

    for (int kt = 0; kt < KT; ++kt) {
        const uint32_t b_s = a_s + A_STAGE_B;
        // next stage pointers (for handoff at kk3/q3)
        const int sn = (s + 1 == STAGES) ? 0 : s + 1;
        const uint32_t a_sn = sb + SMEM_HDR + sn * STAGE_B;
        const int phn = (s + 1 == STAGES) ? (ph ^ 1) : ph;
        const bool last_kt = (kt == KT - 1);

#pragma unroll
        for (int kk = 0; kk < 4; ++kk) {
            const int ap = kk & 1;          // a parity
#pragma unroll
            for (int q = 0; q < 4; ++q) {
                const int bp = (kk * 4 + q) & 1;   // b parity
                // ---- prefetch next fragments ----
                if (q < 3) {
                    ldsm4(bfr[bp ^ 1], b_s + offB0[kk] + (uint32_t)((q + 1) * 2048));
                } else if (kk < 3) {
                    ldsm4(afr[ap ^ 1][0], a_s + offA0[kk + 1]);
                    ldsm4(afr[ap ^ 1][1], a_s + offA0[kk + 1] + 2048);
                    ldsm4(bfr[bp ^ 1], b_s + offB0[kk + 1]);
                } else if (!last_kt) {
                    // stage handoff: wait next FULL, prefetch its kk0 under final MMAs
                    mbar_wait(FULL + 8u * sn, (uint32_t)phn);
                    ldsm4(afr[ap ^ 1][0], a_sn + offA0[0]);
                    ldsm4(afr[ap ^ 1][1], a_sn + offA0[0] + 2048);
                    ldsm4(bfr[bp ^ 1], a_sn + A_STAGE_B + offB0[0]);
                }
                // ---- compute 4 MMAs on current fragments ----
                mma16816(c[0][2 * q + 0], afr[ap][0], bfr[bp][0], bfr[bp][2]);
                mma16816(c[0][2 * q + 1], afr[ap][0], bfr[bp][1], bfr[bp][3]);
                mma16816(c[1][2 * q + 0], afr[ap][1], bfr[bp][0], bfr[bp][2]);
                mma16816(c[1][2 * q + 1], afr[ap][1], bfr[bp][1], bfr[bp][3]);
            }
        }
        // all smem reads from stage s consumed by the MMAs above
        mbar_arrive(EMPTY + 8u * s);
        s = sn; ph = phn; a_s = a_sn;
    }

    // ---- fused epilogue: out = acc*INV + badd[n] + 0.01*noise ----
    const int mBase = tileM * BM + warpM * 32 + (lane >> 2);
    const int nBase = tileN * BN + warpN * 64 + (lane & 3) * 2;
#pragma unroll
    for (int mt = 0; mt < 2; ++mt) {
#pragma unroll
        for (int nt = 0; nt < 8; ++nt) {
#pragma unroll
            for (int half = 0; half < 2; ++half) {
                const int m = mBase + mt * 16 + half * 8;
                const int n = nBase + nt * 8;
                const size_t off = (size_t)m * NDIM + n;
                float2 nz = *reinterpret_cast<const float2*>(noise + off);
                float2 bd = *reinterpret_cast<const float2*>(g_badd + n);
                float2 o;
                o.x = fmaf(c[mt][nt][2 * half + 0], INVSCALE, fmaf(0.01f, nz.x, bd.x));
                o.y = fmaf(c[mt][nt][2 * half + 1], INVSCALE, fmaf(0.01f, nz.y, bd.y));
                *reinterpret_cast<float2*>(out + off) = o;
            }
        }
    }
}

// ---------------- launch ----------------
typedef CUresult (*PFN_tmEncode)(
    CUtensorMap*, CUtensorMapDataType, cuuint32_t, void*,
    const cuuint64_t*, const cuuint64_t*, const cuuint32_t*, const cuuint32_t*,
    CUtensorMapInterleave, CUtensorMapSwizzle, CUtensorMapL2promotion,
    CUtensorMapFloatOOBfill);

extern "C" void kernel_launch(void* const* d_in, const int* in_sizes, int n_in,
                              void* d_out, int out_size) {
    const float* x  = (const float*)d_in[0];   // tensor  [4096,4096]
    const float* w  = (const float*)d_in[1];   // weights [4096,4096]
    const float* b  = (const float*)d_in[2];   // biases  [4096]
    const float* nz = (const float*)d_in[3];   // noise   [4096,4096]
    float* out = (float*)d_out;

    const int qgrid = (NDIM * NDIM / 4) / 256;  // 16384
    quant_kernel<<<qgrid, 256>>>((const float4*)x, 0, 4.0f, 31.75f);
    quant_kernel<<<qgrid, 256>>>((const float4*)w, 1, 1.0f, 127.0f);
    quant_bias_kernel<<<NDIM / 256, 256>>>(b);

    // build tensormaps (host-side, pure; no allocation)
    void* encFn = nullptr;
    cudaDriverEntryPointQueryResult qres;
    cudaGetDriverEntryPoint("cuTensorMapEncodeTiled", &encFn, cudaEnableDefault, &qres);
    PFN_tmEncode enc = (PFN_tmEncode)encFn;

    void *xq_ptr = nullptr, *wq_ptr = nullptr;
    cudaGetSymbolAddress(&xq_ptr, g_Xq);
    cudaGetSymbolAddress(&wq_ptr, g_Wq);

    cuuint64_t dims[2]    = {(cuuint64_t)NDIM, (cuuint64_t)NDIM};
    cuuint64_t strides[1] = {(cuuint64_t)NDIM * 2};
    cuuint32_t box[2]     = {(cuuint32_t)BK, (cuuint32_t)BM};   // 64 elems x 128 rows
    cuuint32_t estr[2]    = {1, 1};

    CUtensorMap tmA, tmB;
    enc(&tmA, CU_TENSOR_MAP_DATA_TYPE_BFLOAT16, 2, xq_ptr, dims, strides, box, estr,
        CU_TENSOR_MAP_INTERLEAVE_NONE, CU_TENSOR_MAP_SWIZZLE_128B,
        CU_TENSOR_MAP_L2_PROMOTION_L2_128B, CU_TENSOR_MAP_FLOAT_OOB_FILL_NONE);
    enc(&tmB, CU_TENSOR_MAP_DATA_TYPE_BFLOAT16, 2, wq_ptr, dims, strides, box, estr,
        CU_TENSOR_MAP_INTERLEAVE_NONE, CU_TENSOR_MAP_SWIZZLE_128B,
        CU_TENSOR_MAP_L2_PROMOTION_L2_128B, CU_TENSOR_MAP_FLOAT_OOB_FILL_NONE);

    cudaFuncSetAttribute(gemm_kernel, cudaFuncAttributeMaxDynamicSharedMemorySize, SMEM_TOTAL);
    dim3 grid(NDIM / BN, NDIM / BM);            // 32 x 32 = 1024 CTAs
    gemm_kernel<<<grid, 288, SMEM_TOTAL>>>(tmA, tmB, nz, out);
}

// round 9
// speedup vs baseline: 1.3456x; 1.3456x over previous
#include <cuda_runtime.h>
#include <cuda.h>
#include <cuda_bf16.h>
#include <stdint.h>

#define DI __device__ __forceinline__

// ---------------- problem constants ----------------
static constexpr int    NDIM     = 4096;
static constexpr float  INVSCALE = 1.0f / (31.75f * 127.0f);   // 1/(sx*sw)

// ---------------- GEMM tiling (bf16 HMMA + TMA, warp-specialized) ----------------
static constexpr int BM = 128, BN = 128, BK = 64;
static constexpr int STAGES = 3;
static constexpr int KT = NDIM / BK;                    // 64 k-iterations
static constexpr int A_STAGE_B = BM * 128;              // 16384 (128 rows x 128B)
static constexpr int B_STAGE_B = BN * 128;              // 16384
static constexpr int STAGE_B   = A_STAGE_B + B_STAGE_B; // 32768
static constexpr int SMEM_HDR  = 1024;
static constexpr int SMEM_TOTAL = SMEM_HDR + STAGES * STAGE_B;  // 99328
static constexpr int NCONS = 128;                       // consumer threads (4 warps, 64x64 tiles)

// ---------------- device scratch (allocation-free rule) ----------------
__device__ __nv_bfloat16 g_Xq[(size_t)NDIM * NDIM];   // quantized activations (integer-valued bf16)
__device__ __nv_bfloat16 g_Wq[(size_t)NDIM * NDIM];   // quantized weights (integer-valued bf16)
__device__ float         g_badd[NDIM];                // epilogue bias term

// ---------------- PTX helpers ----------------
DI uint32_t smem_u32(const void* p) {
    uint32_t a;
    asm("{ .reg .u64 t; cvta.to.shared.u64 t, %1; cvt.u32.u64 %0, t; }" : "=r"(a) : "l"(p));
    return a;
}
DI void ldsm4(uint32_t* r, uint32_t addr) {
    asm volatile("ldmatrix.sync.aligned.m8n8.x4.shared.b16 {%0,%1,%2,%3}, [%4];"
                 : "=r"(r[0]), "=r"(r[1]), "=r"(r[2]), "=r"(r[3]) : "r"(addr));
}
DI void mma16816(float* c, const uint32_t* a, uint32_t b0, uint32_t b1) {
    asm volatile(
        "mma.sync.aligned.m16n8k16.row.col.f32.bf16.bf16.f32 "
        "{%0,%1,%2,%3}, {%4,%5,%6,%7}, {%8,%9}, {%0,%1,%2,%3};"
        : "+f"(c[0]), "+f"(c[1]), "+f"(c[2]), "+f"(c[3])
        : "r"(a[0]), "r"(a[1]), "r"(a[2]), "r"(a[3]), "r"(b0), "r"(b1));
}
// SW128 swizzled byte offset: 128B rows, 16B chunk c in [0,8)
DI uint32_t sw_off(int row, int c) {
    return (uint32_t)(row * 128 + ((c ^ (row & 7)) << 4));
}
DI void mbar_init(uint32_t a, uint32_t cnt) {
    asm volatile("mbarrier.init.shared.b64 [%0], %1;" :: "r"(a), "r"(cnt) : "memory");
}
DI void mbar_expect(uint32_t a, uint32_t bytes) {
    asm volatile("mbarrier.arrive.expect_tx.shared.b64 _, [%0], %1;"
                 :: "r"(a), "r"(bytes) : "memory");
}
DI void mbar_arrive(uint32_t a) {
    asm volatile("mbarrier.arrive.shared.b64 _, [%0];" :: "r"(a) : "memory");
}
DI void mbar_wait(uint32_t a, uint32_t parity) {
    asm volatile(
        "{\n\t.reg .pred P;\n"
        "WL_%=:\n\t"
        "mbarrier.try_wait.parity.acquire.cta.shared::cta.b64 P, [%0], %1, 0x989680;\n\t"
        "@P bra WD_%=;\n\t"
        "bra WL_%=;\n"
        "WD_%=:\n\t}"
        :: "r"(a), "r"(parity) : "memory");
}
DI void tma2d(uint32_t dst, const CUtensorMap* tm, int cx, int cy, uint32_t mbar) {
    asm volatile(
        "cp.async.bulk.tensor.2d.shared::cluster.global.tile.mbarrier::complete_tx::bytes "
        "[%0], [%1, {%2, %3}], [%4];"
        :: "r"(dst), "l"(tm), "r"(cx), "r"(cy), "r"(mbar) : "memory");
}

// ---------------- quantize kernels ----------------
__global__ void quant_kernel(const float4* __restrict__ src, int which,
                             float clip, float scale) {
    size_t i = (size_t)blockIdx.x * blockDim.x + threadIdx.x;
    float4 v = src[i];
    float a0 = rintf(fminf(clip, fmaxf(-clip, v.x)) * scale);
    float a1 = rintf(fminf(clip, fmaxf(-clip, v.y)) * scale);
    float a2 = rintf(fminf(clip, fmaxf(-clip, v.z)) * scale);
    float a3 = rintf(fminf(clip, fmaxf(-clip, v.w)) * scale);
    __nv_bfloat162 p0 = __floats2bfloat162_rn(a0, a1);
    __nv_bfloat162 p1 = __floats2bfloat162_rn(a2, a3);
    uint2 o;
    o.x = *reinterpret_cast<uint32_t*>(&p0);
    o.y = *reinterpret_cast<uint32_t*>(&p1);
    uint2* dst = reinterpret_cast<uint2*>(which ? g_Wq : g_Xq);
    dst[i] = o;
}

__global__ void quant_bias_kernel(const float* __restrict__ b) {
    int i = blockIdx.x * blockDim.x + threadIdx.x;
    float q = rintf(fminf(1.0f, fmaxf(-1.0f, b[i])) * 127.0f);
    g_badd[i] = 32.0f * q * INVSCALE;   // quantized ones-column (=32) * quantized bias
}

// ---------------- GEMM: producer warp (TMA) + 4 consumer warps (64x64 HMMA) ----------------
__global__ __launch_bounds__(160, 2)
void gemm_kernel(const __grid_constant__ CUtensorMap tmA,
                 const __grid_constant__ CUtensorMap tmB,
                 const float* __restrict__ noise, float* __restrict__ out) {
    extern __shared__ __align__(1024) char smem[];
    const uint32_t sb = smem_u32(smem);
    const int tid  = threadIdx.x;
    const int lane = tid & 31;

    const uint32_t FULL  = sb;       // full[s]  at sb + 8*s
    const uint32_t EMPTY = sb + 24;  // empty[s] at sb + 24 + 8*s

    if (tid == 0) {
#pragma unroll
        for (int s = 0; s < STAGES; ++s) {
            mbar_init(FULL + 8u * s, 1);
            mbar_init(EMPTY + 8u * s, NCONS);
        }
        asm volatile("fence.mbarrier_init.release.cluster;" ::: "memory");
    }
    __syncthreads();

    const int tileM = blockIdx.y, tileN = blockIdx.x;

    if (tid >= NCONS) {
        // ================= producer warp (lane 0 only) =================
        if (lane == 0) {
#pragma unroll
            for (int f = 0; f < STAGES; ++f) {
                const uint32_t a_s = sb + SMEM_HDR + f * STAGE_B;
                mbar_expect(FULL + 8u * f, (uint32_t)STAGE_B);
                tma2d(a_s,             &tmA, f * BK, tileM * BM, FULL + 8u * f);
                tma2d(a_s + A_STAGE_B, &tmB, f * BK, tileN * BN, FULL + 8u * f);
            }
            int s = 0, php = 0;
            for (int f = STAGES; f < KT; ++f) {
                const uint32_t a_s = sb + SMEM_HDR + s * STAGE_B;
                mbar_wait(EMPTY + 8u * s, (uint32_t)php);
                mbar_expect(FULL + 8u * s, (uint32_t)STAGE_B);
                tma2d(a_s,             &tmA, f * BK, tileM * BM, FULL + 8u * s);
                tma2d(a_s + A_STAGE_B, &tmB, f * BK, tileN * BN, FULL + 8u * s);
                if (++s == STAGES) { s = 0; php ^= 1; }
            }
        }
        return;
    }

    // ================= consumer warps: 2x2 grid of 64x64 tiles =================
    const int warp  = tid >> 5;      // 0..3
    const int warpM = warp >> 1;     // 0..1, 64 rows each
    const int warpN = warp & 1;      // 0..1, 64 cols each

    float c[4][8][4];                // 4 m16 x 8 n8 accumulators (128 regs)
#pragma unroll
    for (int i = 0; i < 4; ++i)
#pragma unroll
        for (int j = 0; j < 8; ++j)
#pragma unroll
            for (int k = 0; k < 4; ++k) c[i][j][k] = 0.0f;

    // per-lane swizzled ldmatrix base offsets (swizzle invariant under row+16 => +2048B)
    const int lrow = lane & 15;
    const int csel = lane >> 4;
    uint32_t offA0[4], offB0[4];
    {
        const int rA = warpM * 64 + lrow;
        const int rB = warpN * 64 + lrow;
#pragma unroll
        for (int kk = 0; kk < 4; ++kk) {
            offA0[kk] = sw_off(rA, (kk << 1) | csel);
            offB0[kk] = sw_off(rB, (kk << 1) | csel);
        }
    }

    int s = 0, ph = 0;
    for (int kt = 0; kt < KT; ++kt) {
        const uint32_t a_s = sb + SMEM_HDR + s * STAGE_B;
        const uint32_t b_s = a_s + A_STAGE_B;

        mbar_wait(FULL + 8u * s, (uint32_t)ph);

#pragma unroll
        for (int kk = 0; kk < 4; ++kk) {
            uint32_t a[4][4], b[4][4];
#pragma unroll
            for (int h = 0; h < 4; ++h)
                ldsm4(a[h], a_s + offA0[kk] + (uint32_t)(h * 2048));
#pragma unroll
            for (int q = 0; q < 4; ++q)
                ldsm4(b[q], b_s + offB0[kk] + (uint32_t)(q * 2048));
#pragma unroll
            for (int h = 0; h < 4; ++h) {
#pragma unroll
                for (int q = 0; q < 4; ++q) {
                    mma16816(c[h][2 * q + 0], a[h], b[q][0], b[q][2]);
                    mma16816(c[h][2 * q + 1], a[h], b[q][1], b[q][3]);
                }
            }
        }

        mbar_arrive(EMPTY + 8u * s);
        if (++s == STAGES) { s = 0; ph ^= 1; }
    }

    // ---- fused epilogue: out = acc*INV + badd[n] + 0.01*noise ----
    const int mBase = tileM * BM + warpM * 64 + (lane >> 2);
    const int nBase = tileN * BN + warpN * 64 + (lane & 3) * 2;
#pragma unroll
    for (int h = 0; h < 4; ++h) {
#pragma unroll
        for (int nt = 0; nt < 8; ++nt) {
#pragma unroll
            for (int half = 0; half < 2; ++half) {
                const int m = mBase + h * 16 + half * 8;
                const int n = nBase + nt * 8;
                const size_t off = (size_t)m * NDIM + n;
                float2 nz = *reinterpret_cast<const float2*>(noise + off);
                float2 bd = *reinterpret_cast<const float2*>(g_badd + n);
                float2 o;
                o.x = fmaf(c[h][nt][2 * half + 0], INVSCALE, fmaf(0.01f, nz.x, bd.x));
                o.y = fmaf(c[h][nt][2 * half + 1], INVSCALE, fmaf(0.01f, nz.y, bd.y));
                *reinterpret_cast<float2*>(out + off) = o;
            }
        }
    }
}

// ---------------- launch ----------------
typedef CUresult (*PFN_tmEncode)(
    CUtensorMap*, CUtensorMapDataType, cuuint32_t, void*,
    const cuuint64_t*, const cuuint64_t*, const cuuint32_t*, const cuuint32_t*,
    CUtensorMapInterleave, CUtensorMapSwizzle, CUtensorMapL2promotion,
    CUtensorMapFloatOOBfill);

extern "C" void kernel_launch(void* const* d_in, const int* in_sizes, int n_in,
                              void* d_out, int out_size) {
    const float* x  = (const float*)d_in[0];   // tensor  [4096,4096]
    const float* w  = (const float*)d_in[1];   // weights [4096,4096]
    const float* b  = (const float*)d_in[2];   // biases  [4096]
    const float* nz = (const float*)d_in[3];   // noise   [4096,4096]
    float* out = (float*)d_out;

    const int qgrid = (NDIM * NDIM / 4) / 256;  // 16384
    quant_kernel<<<qgrid, 256>>>((const float4*)x, 0, 4.0f, 31.75f);
    quant_kernel<<<qgrid, 256>>>((const float4*)w, 1, 1.0f, 127.0f);
    quant_bias_kernel<<<NDIM / 256, 256>>>(b);

    // build tensormaps (host-side, pure; no allocation)
    void* encFn = nullptr;
    cudaDriverEntryPointQueryResult qres;
    cudaGetDriverEntryPoint("cuTensorMapEncodeTiled", &encFn, cudaEnableDefault, &qres);
    PFN_tmEncode enc = (PFN_tmEncode)encFn;

    void *xq_ptr = nullptr, *wq_ptr = nullptr;
    cudaGetSymbolAddress(&xq_ptr, g_Xq);
    cudaGetSymbolAddress(&wq_ptr, g_Wq);

    cuuint64_t dims[2]    = {(cuuint64_t)NDIM, (cuuint64_t)NDIM};
    cuuint64_t strides[1] = {(cuuint64_t)NDIM * 2};
    cuuint32_t box[2]     = {(cuuint32_t)BK, (cuuint32_t)BM};   // 64 elems x 128 rows
    cuuint32_t estr[2]    = {1, 1};

    CUtensorMap tmA, tmB;
    enc(&tmA, CU_TENSOR_MAP_DATA_TYPE_BFLOAT16, 2, xq_ptr, dims, strides, box, estr,
        CU_TENSOR_MAP_INTERLEAVE_NONE, CU_TENSOR_MAP_SWIZZLE_128B,
        CU_TENSOR_MAP_L2_PROMOTION_L2_128B, CU_TENSOR_MAP_FLOAT_OOB_FILL_NONE);
    enc(&tmB, CU_TENSOR_MAP_DATA_TYPE_BFLOAT16, 2, wq_ptr, dims, strides, box, estr,
        CU_TENSOR_MAP_INTERLEAVE_NONE, CU_TENSOR_MAP_SWIZZLE_128B,
        CU_TENSOR_MAP_L2_PROMOTION_L2_128B, CU_TENSOR_MAP_FLOAT_OOB_FILL_NONE);

    cudaFuncSetAttribute(gemm_kernel, cudaFuncAttributeMaxDynamicSharedMemorySize, SMEM_TOTAL);
    dim3 grid(NDIM / BN, NDIM / BM);            // 32 x 32 = 1024 CTAs
    gemm_kernel<<<grid, 160, SMEM_TOTAL>>>(tmA, tmB, nz, out);
}

// round 10
// speedup vs baseline: 1.4436x; 1.0728x over previous
#include <cuda_runtime.h>
#include <cuda.h>
#include <cuda_bf16.h>
#include <stdint.h>

#define DI __device__ __forceinline__

// ---------------- problem constants ----------------
static constexpr int    NDIM     = 4096;
static constexpr float  INVSCALE = 1.0f / (31.75f * 127.0f);   // 1/(sx*sw)

// ---------------- GEMM tiling (bf16 HMMA + TMA, warp-specialized) ----------------
static constexpr int BM = 128, BN = 128, BK = 64;
static constexpr int STAGES = 3;
static constexpr int KT = NDIM / BK;                    // 64 k-iterations
static constexpr int A_STAGE_B = BM * 128;              // 16384 (128 rows x 128B)
static constexpr int B_STAGE_B = BN * 128;              // 16384
static constexpr int STAGE_B   = A_STAGE_B + B_STAGE_B; // 32768
static constexpr int SMEM_HDR  = 1024;
static constexpr int SMEM_TOTAL = SMEM_HDR + STAGES * STAGE_B;  // 99328
static constexpr int NCONS = 256;                       // consumer threads

// ---------------- device scratch (allocation-free rule) ----------------
__device__ __nv_bfloat16 g_Xq[(size_t)NDIM * NDIM];   // quantized activations (integer-valued bf16)
__device__ __nv_bfloat16 g_Wq[(size_t)NDIM * NDIM];   // quantized weights (integer-valued bf16)
__device__ float         g_badd[NDIM];                // epilogue bias term

// ---------------- PTX helpers ----------------
DI uint32_t smem_u32(const void* p) {
    uint32_t a;
    asm("{ .reg .u64 t; cvta.to.shared.u64 t, %1; cvt.u32.u64 %0, t; }" : "=r"(a) : "l"(p));
    return a;
}
DI void ldsm4(uint32_t* r, uint32_t addr) {
    asm volatile("ldmatrix.sync.aligned.m8n8.x4.shared.b16 {%0,%1,%2,%3}, [%4];"
                 : "=r"(r[0]), "=r"(r[1]), "=r"(r[2]), "=r"(r[3]) : "r"(addr));
}
DI void mma16816(float* c, const uint32_t* a, uint32_t b0, uint32_t b1) {
    asm volatile(
        "mma.sync.aligned.m16n8k16.row.col.f32.bf16.bf16.f32 "
        "{%0,%1,%2,%3}, {%4,%5,%6,%7}, {%8,%9}, {%0,%1,%2,%3};"
        : "+f"(c[0]), "+f"(c[1]), "+f"(c[2]), "+f"(c[3])
        : "r"(a[0]), "r"(a[1]), "r"(a[2]), "r"(a[3]), "r"(b0), "r"(b1));
}
// SW128 swizzled byte offset: 128B rows, 16B chunk c in [0,8)
DI uint32_t sw_off(int row, int c) {
    return (uint32_t)(row * 128 + ((c ^ (row & 7)) << 4));
}
DI void mbar_init(uint32_t a, uint32_t cnt) {
    asm volatile("mbarrier.init.shared.b64 [%0], %1;" :: "r"(a), "r"(cnt) : "memory");
}
DI void mbar_expect(uint32_t a, uint32_t bytes) {
    asm volatile("mbarrier.arrive.expect_tx.shared.b64 _, [%0], %1;"
                 :: "r"(a), "r"(bytes) : "memory");
}
DI void mbar_arrive(uint32_t a) {
    asm volatile("mbarrier.arrive.release.cta.shared::cta.b64 _, [%0];" :: "r"(a) : "memory");
}
DI void mbar_wait(uint32_t a, uint32_t parity) {
    asm volatile(
        "{\n\t.reg .pred P;\n"
        "WL_%=:\n\t"
        "mbarrier.try_wait.parity.acquire.cta.shared::cta.b64 P, [%0], %1, 0x989680;\n\t"
        "@P bra WD_%=;\n\t"
        "bra WL_%=;\n"
        "WD_%=:\n\t}"
        :: "r"(a), "r"(parity) : "memory");
}
DI void tma2d(uint32_t dst, const CUtensorMap* tm, int cx, int cy, uint32_t mbar) {
    asm volatile(
        "cp.async.bulk.tensor.2d.shared::cluster.global.tile.mbarrier::complete_tx::bytes "
        "[%0], [%1, {%2, %3}], [%4];"
        :: "r"(dst), "l"(tm), "r"(cx), "r"(cy), "r"(mbar) : "memory");
}

// ---------------- quantize kernels ----------------
__global__ void quant_kernel(const float4* __restrict__ src, int which,
                             float clip, float scale) {
    size_t i = (size_t)blockIdx.x * blockDim.x + threadIdx.x;
    float4 v = src[i];
    float a0 = rintf(fminf(clip, fmaxf(-clip, v.x)) * scale);
    float a1 = rintf(fminf(clip, fmaxf(-clip, v.y)) * scale);
    float a2 = rintf(fminf(clip, fmaxf(-clip, v.z)) * scale);
    float a3 = rintf(fminf(clip, fmaxf(-clip, v.w)) * scale);
    __nv_bfloat162 p0 = __floats2bfloat162_rn(a0, a1);
    __nv_bfloat162 p1 = __floats2bfloat162_rn(a2, a3);
    uint2 o;
    o.x = *reinterpret_cast<uint32_t*>(&p0);
    o.y = *reinterpret_cast<uint32_t*>(&p1);
    uint2* dst = reinterpret_cast<uint2*>(which ? g_Wq : g_Xq);
    dst[i] = o;
}

__global__ void quant_bias_kernel(const float* __restrict__ b) {
    int i = blockIdx.x * blockDim.x + threadIdx.x;
    float q = rintf(fminf(1.0f, fmaxf(-1.0f, b[i])) * 127.0f);
    g_badd[i] = 32.0f * q * INVSCALE;   // quantized ones-column (=32) * quantized bias
}

// ---------------- GEMM: producer warp (TMA) + 8 consumer warps (HMMA) ----------------
__global__ __launch_bounds__(288, 2)
void gemm_kernel(const __grid_constant__ CUtensorMap tmA,
                 const __grid_constant__ CUtensorMap tmB,
                 const float* __restrict__ noise, float* __restrict__ out) {
    extern __shared__ __align__(1024) char smem[];
    const uint32_t sb = smem_u32(smem);
    const int tid  = threadIdx.x;
    const int lane = tid & 31;

    const uint32_t FULL  = sb;       // full[s]  at sb + 8*s
    const uint32_t EMPTY = sb + 24;  // empty[s] at sb + 24 + 8*s

    if (tid == 0) {
#pragma unroll
        for (int s = 0; s < STAGES; ++s) {
            mbar_init(FULL + 8u * s, 1);
            mbar_init(EMPTY + 8u * s, NCONS);
        }
        asm volatile("fence.mbarrier_init.release.cluster;" ::: "memory");
    }
    __syncthreads();

    const int tileM = blockIdx.y, tileN = blockIdx.x;

    if (tid >= NCONS) {
        // ================= producer warp (lane 0 only) =================
        if (lane == 0) {
#pragma unroll
            for (int f = 0; f < STAGES; ++f) {
                const uint32_t a_s = sb + SMEM_HDR + f * STAGE_B;
                mbar_expect(FULL + 8u * f, (uint32_t)STAGE_B);
                tma2d(a_s,             &tmA, f * BK, tileM * BM, FULL + 8u * f);
                tma2d(a_s + A_STAGE_B, &tmB, f * BK, tileN * BN, FULL + 8u * f);
            }
            int s = 0, php = 0;
            for (int f = STAGES; f < KT; ++f) {
                const uint32_t a_s = sb + SMEM_HDR + s * STAGE_B;
                mbar_wait(EMPTY + 8u * s, (uint32_t)php);
                mbar_expect(FULL + 8u * s, (uint32_t)STAGE_B);
                tma2d(a_s,             &tmA, f * BK, tileM * BM, FULL + 8u * s);
                tma2d(a_s + A_STAGE_B, &tmB, f * BK, tileN * BN, FULL + 8u * s);
                if (++s == STAGES) { s = 0; php ^= 1; }
            }
        }
        return;
    }

    // ================= consumer warps =================
    const int warp  = tid >> 5;
    const int warpM = warp >> 1;     // 0..3, 32 rows each
    const int warpN = warp & 1;      // 0..1, 64 cols each
    // kk phase: anti-phase same-SMSP warp pairs (w and w+4 share an SMSP)
    const int phase = ((warp & 3) ^ ((warp >> 2) << 1)) & 3;

    float c[2][8][4];
#pragma unroll
    for (int i = 0; i < 2; ++i)
#pragma unroll
        for (int j = 0; j < 8; ++j)
#pragma unroll
            for (int k = 0; k < 4; ++k) c[i][j][k] = 0.0f;

    // per-lane swizzled ldmatrix base offsets (swizzle invariant under row+16 => +2048B)
    const int lrow = lane & 15;
    const int csel = lane >> 4;
    uint32_t offA0[4], offB0[4];     // indexed by physical kk
    {
        const int rA = warpM * 32 + lrow;
        const int rB = warpN * 64 + lrow;
#pragma unroll
        for (int kk = 0; kk < 4; ++kk) {
            offA0[kk] = sw_off(rA, (kk << 1) | csel);
            offB0[kk] = sw_off(rB, (kk << 1) | csel);
        }
    }

    int s = 0, ph = 0;
    for (int kt = 0; kt < KT; ++kt) {
        const uint32_t a_s = sb + SMEM_HDR + s * STAGE_B;
        const uint32_t b_s = a_s + A_STAGE_B;

        mbar_wait(FULL + 8u * s, (uint32_t)ph);

#pragma unroll
        for (int i = 0; i < 4; ++i) {
            const int kk = (i + phase) & 3;          // staggered order, exact-sum safe
            uint32_t a[2][4], b[4][4];
            ldsm4(a[0], a_s + offA0[kk]);
            ldsm4(a[1], a_s + offA0[kk] + 2048);
#pragma unroll
            for (int q = 0; q < 4; ++q)
                ldsm4(b[q], b_s + offB0[kk] + (uint32_t)(q * 2048));
            if (i == 3) mbar_arrive(EMPTY + 8u * s); // all stage reads issued (release)
#pragma unroll
            for (int q = 0; q < 4; ++q) {
                mma16816(c[0][2 * q + 0], a[0], b[q][0], b[q][2]);
                mma16816(c[0][2 * q + 1], a[0], b[q][1], b[q][3]);
                mma16816(c[1][2 * q + 0], a[1], b[q][0], b[q][2]);
                mma16816(c[1][2 * q + 1], a[1], b[q][1], b[q][3]);
            }
        }

        if (++s == STAGES) { s = 0; ph ^= 1; }
    }

    // ---- fused epilogue: out = acc*INV + badd[n] + 0.01*noise ----
    const int mBase = tileM * BM + warpM * 32 + (lane >> 2);
    const int nBase = tileN * BN + warpN * 64 + (lane & 3) * 2;
#pragma unroll
    for (int mt = 0; mt < 2; ++mt) {
#pragma unroll
        for (int nt = 0; nt < 8; ++nt) {
#pragma unroll
            for (int half = 0; half < 2; ++half) {
                const int m = mBase + mt * 16 + half * 8;
                const int n = nBase + nt * 8;
                const size_t off = (size_t)m * NDIM + n;
                float2 nz = *reinterpret_cast<const float2*>(noise + off);
                float2 bd = *reinterpret_cast<const float2*>(g_badd + n);
                float2 o;
                o.x = fmaf(c[mt][nt][2 * half + 0], INVSCALE, fmaf(0.01f, nz.x, bd.x));
                o.y = fmaf(c[mt][nt][2 * half + 1], INVSCALE, fmaf(0.01f, nz.y, bd.y));
                *reinterpret_cast<float2*>(out + off) = o;
            }
        }
    }
}

// ---------------- launch ----------------
typedef CUresult (*PFN_tmEncode)(
    CUtensorMap*, CUtensorMapDataType, cuuint32_t, void*,
    const cuuint64_t*, const cuuint64_t*, const cuuint32_t*, const cuuint32_t*,
    CUtensorMapInterleave, CUtensorMapSwizzle, CUtensorMapL2promotion,
    CUtensorMapFloatOOBfill);

extern "C" void kernel_launch(void* const* d_in, const int* in_sizes, int n_in,
                              void* d_out, int out_size) {
    const float* x  = (const float*)d_in[0];   // tensor  [4096,4096]
    const float* w  = (const float*)d_in[1];   // weights [4096,4096]
    const float* b  = (const float*)d_in[2];   // biases  [4096]
    const float* nz = (const float*)d_in[3];   // noise   [4096,4096]
    float* out = (float*)d_out;

    const int qgrid = (NDIM * NDIM / 4) / 256;  // 16384
    quant_kernel<<<qgrid, 256>>>((const float4*)x, 0, 4.0f, 31.75f);
    quant_kernel<<<qgrid, 256>>>((const float4*)w, 1, 1.0f, 127.0f);
    quant_bias_kernel<<<NDIM / 256, 256>>>(b);

    // build tensormaps (host-side, pure; no allocation)
    void* encFn = nullptr;
    cudaDriverEntryPointQueryResult qres;
    cudaGetDriverEntryPoint("cuTensorMapEncodeTiled", &encFn, cudaEnableDefault, &qres);
    PFN_tmEncode enc = (PFN_tmEncode)encFn;

    void *xq_ptr = nullptr, *wq_ptr = nullptr;
    cudaGetSymbolAddress(&xq_ptr, g_Xq);
    cudaGetSymbolAddress(&wq_ptr, g_Wq);

    cuuint64_t dims[2]    = {(cuuint64_t)NDIM, (cuuint64_t)NDIM};
    cuuint64_t strides[1] = {(cuuint64_t)NDIM * 2};
    cuuint32_t box[2]     = {(cuuint32_t)BK, (cuuint32_t)BM};   // 64 elems x 128 rows
    cuuint32_t estr[2]    = {1, 1};

    CUtensorMap tmA, tmB;
    enc(&tmA, CU_TENSOR_MAP_DATA_TYPE_BFLOAT16, 2, xq_ptr, dims, strides, box, estr,
        CU_TENSOR_MAP_INTERLEAVE_NONE, CU_TENSOR_MAP_SWIZZLE_128B,
        CU_TENSOR_MAP_L2_PROMOTION_L2_128B, CU_TENSOR_MAP_FLOAT_OOB_FILL_NONE);
    enc(&tmB, CU_TENSOR_MAP_DATA_TYPE_BFLOAT16, 2, wq_ptr, dims, strides, box, estr,
        CU_TENSOR_MAP_INTERLEAVE_NONE, CU_TENSOR_MAP_SWIZZLE_128B,
        CU_TENSOR_MAP_L2_PROMOTION_L2_128B, CU_TENSOR_MAP_FLOAT_OOB_FILL_NONE);

    cudaFuncSetAttribute(gemm_kernel, cudaFuncAttributeMaxDynamicSharedMemorySize, SMEM_TOTAL);
    dim3 grid(NDIM / BN, NDIM / BM);            // 32 x 32 = 1024 CTAs
    gemm_kernel<<<grid, 288, SMEM_TOTAL>>>(tmA, tmB, nz, out);
}

// round 11
// speedup vs baseline: 1.5830x; 1.0966x over previous
#include <cuda_runtime.h>
#include <cuda.h>
#include <cuda_bf16.h>
#include <stdint.h>

#define DI __device__ __forceinline__

// ---------------- problem constants ----------------
static constexpr int    NDIM     = 4096;
static constexpr float  INVSCALE = 1.0f / (31.75f * 127.0f);   // 1/(sx*sw)

// ---------------- GEMM tiling (bf16 HMMA + TMA, warp-specialized, split-K=2) ----------------
static constexpr int BM = 128, BN = 128, BK = 64;
static constexpr int STAGES = 3;
static constexpr int KSPLIT = 2;
static constexpr int KT_HALF = NDIM / BK / KSPLIT;      // 32 k-iterations per half
static constexpr int A_STAGE_B = BM * 128;              // 16384 (128 rows x 128B)
static constexpr int B_STAGE_B = BN * 128;              // 16384
static constexpr int STAGE_B   = A_STAGE_B + B_STAGE_B; // 32768
static constexpr int SMEM_HDR  = 1024;
static constexpr int SMEM_TOTAL = SMEM_HDR + STAGES * STAGE_B;  // 99328
static constexpr int NCONS = 256;                       // consumer threads
static constexpr int NTILES = (NDIM / BM) * (NDIM / BN);        // 1024

// ---------------- device scratch (allocation-free rule) ----------------
__device__ __nv_bfloat16 g_Xq[(size_t)NDIM * NDIM];   // quantized activations (integer-valued bf16)
__device__ __nv_bfloat16 g_Wq[(size_t)NDIM * NDIM];   // quantized weights (integer-valued bf16)
__device__ float         g_badd[NDIM];                // epilogue bias term
__device__ float         g_part[(size_t)NDIM * NDIM]; // split-K partials (raw fp32 acc)
__device__ int           g_flag[NTILES];              // half-0 completion flags

// ---------------- PTX helpers ----------------
DI uint32_t smem_u32(const void* p) {
    uint32_t a;
    asm("{ .reg .u64 t; cvta.to.shared.u64 t, %1; cvt.u32.u64 %0, t; }" : "=r"(a) : "l"(p));
    return a;
}
DI void ldsm4(uint32_t* r, uint32_t addr) {
    asm volatile("ldmatrix.sync.aligned.m8n8.x4.shared.b16 {%0,%1,%2,%3}, [%4];"
                 : "=r"(r[0]), "=r"(r[1]), "=r"(r[2]), "=r"(r[3]) : "r"(addr));
}
DI void mma16816(float* c, const uint32_t* a, uint32_t b0, uint32_t b1) {
    asm volatile(
        "mma.sync.aligned.m16n8k16.row.col.f32.bf16.bf16.f32 "
        "{%0,%1,%2,%3}, {%4,%5,%6,%7}, {%8,%9}, {%0,%1,%2,%3};"
        : "+f"(c[0]), "+f"(c[1]), "+f"(c[2]), "+f"(c[3])
        : "r"(a[0]), "r"(a[1]), "r"(a[2]), "r"(a[3]), "r"(b0), "r"(b1));
}
// SW128 swizzled byte offset: 128B rows, 16B chunk c in [0,8)
DI uint32_t sw_off(int row, int c) {
    return (uint32_t)(row * 128 + ((c ^ (row & 7)) << 4));
}
DI void mbar_init(uint32_t a, uint32_t cnt) {
    asm volatile("mbarrier.init.shared.b64 [%0], %1;" :: "r"(a), "r"(cnt) : "memory");
}
DI void mbar_expect(uint32_t a, uint32_t bytes) {
    asm volatile("mbarrier.arrive.expect_tx.shared.b64 _, [%0], %1;"
                 :: "r"(a), "r"(bytes) : "memory");
}
DI void mbar_arrive(uint32_t a) {
    asm volatile("mbarrier.arrive.shared.b64 _, [%0];" :: "r"(a) : "memory");
}
DI void mbar_wait(uint32_t a, uint32_t parity) {
    asm volatile(
        "{\n\t.reg .pred P;\n"
        "WL_%=:\n\t"
        "mbarrier.try_wait.parity.acquire.cta.shared::cta.b64 P, [%0], %1, 0x989680;\n\t"
        "@P bra WD_%=;\n\t"
        "bra WL_%=;\n"
        "WD_%=:\n\t}"
        :: "r"(a), "r"(parity) : "memory");
}
DI void tma2d(uint32_t dst, const CUtensorMap* tm, int cx, int cy, uint32_t mbar) {
    asm volatile(
        "cp.async.bulk.tensor.2d.shared::cluster.global.tile.mbarrier::complete_tx::bytes "
        "[%0], [%1, {%2, %3}], [%4];"
        :: "r"(dst), "l"(tm), "r"(cx), "r"(cy), "r"(mbar) : "memory");
}

// ---------------- quantize kernels ----------------
__global__ void quant_kernel(const float4* __restrict__ src, int which,
                             float clip, float scale) {
    size_t i = (size_t)blockIdx.x * blockDim.x + threadIdx.x;
    float4 v = src[i];
    float a0 = rintf(fminf(clip, fmaxf(-clip, v.x)) * scale);
    float a1 = rintf(fminf(clip, fmaxf(-clip, v.y)) * scale);
    float a2 = rintf(fminf(clip, fmaxf(-clip, v.z)) * scale);
    float a3 = rintf(fminf(clip, fmaxf(-clip, v.w)) * scale);
    __nv_bfloat162 p0 = __floats2bfloat162_rn(a0, a1);
    __nv_bfloat162 p1 = __floats2bfloat162_rn(a2, a3);
    uint2 o;
    o.x = *reinterpret_cast<uint32_t*>(&p0);
    o.y = *reinterpret_cast<uint32_t*>(&p1);
    uint2* dst = reinterpret_cast<uint2*>(which ? g_Wq : g_Xq);
    dst[i] = o;
}

__global__ void quant_bias_kernel(const float* __restrict__ b) {
    int i = blockIdx.x * blockDim.x + threadIdx.x;
    float q = rintf(fminf(1.0f, fmaxf(-1.0f, b[i])) * 127.0f);
    g_badd[i] = 32.0f * q * INVSCALE;   // quantized ones-column (=32) * quantized bias
}

__global__ void flag_clear_kernel() {
    g_flag[blockIdx.x * blockDim.x + threadIdx.x] = 0;
}

// ---------------- GEMM: producer warp (TMA) + 8 consumer warps (HMMA), split-K ----------------
__global__ __launch_bounds__(288, 2)
void gemm_kernel(const __grid_constant__ CUtensorMap tmA,
                 const __grid_constant__ CUtensorMap tmB,
                 const float* __restrict__ noise, float* __restrict__ out) {
    extern __shared__ __align__(1024) char smem[];
    const uint32_t sb = smem_u32(smem);
    const int tid  = threadIdx.x;
    const int lane = tid & 31;

    const int bid   = blockIdx.x;
    const int tile  = bid >> 1;          // paired: 2t = half0, 2t+1 = half1
    const int ks    = bid & 1;
    const int tileM = tile >> 5;
    const int tileN = tile & 31;
    const int kbase = ks * KT_HALF;      // in units of BK

    const uint32_t FULL  = sb;       // full[s]  at sb + 8*s
    const uint32_t EMPTY = sb + 24;  // empty[s] at sb + 24 + 8*s

    if (tid == 0) {
#pragma unroll
        for (int s = 0; s < STAGES; ++s) {
            mbar_init(FULL + 8u * s, 1);
            mbar_init(EMPTY + 8u * s, NCONS);
        }
        asm volatile("fence.mbarrier_init.release.cluster;" ::: "memory");
    }
    __syncthreads();

    if (tid >= NCONS) {
        // ================= producer warp (lane 0 only) =================
        if (lane == 0) {
#pragma unroll
            for (int i = 0; i < STAGES; ++i) {
                const uint32_t a_s = sb + SMEM_HDR + i * STAGE_B;
                mbar_expect(FULL + 8u * i, (uint32_t)STAGE_B);
                tma2d(a_s,             &tmA, (kbase + i) * BK, tileM * BM, FULL + 8u * i);
                tma2d(a_s + A_STAGE_B, &tmB, (kbase + i) * BK, tileN * BN, FULL + 8u * i);
            }
            int s = 0, php = 0;
            for (int f = STAGES; f < KT_HALF; ++f) {
                const uint32_t a_s = sb + SMEM_HDR + s * STAGE_B;
                mbar_wait(EMPTY + 8u * s, (uint32_t)php);
                mbar_expect(FULL + 8u * s, (uint32_t)STAGE_B);
                tma2d(a_s,             &tmA, (kbase + f) * BK, tileM * BM, FULL + 8u * s);
                tma2d(a_s + A_STAGE_B, &tmB, (kbase + f) * BK, tileN * BN, FULL + 8u * s);
                if (++s == STAGES) { s = 0; php ^= 1; }
            }
        }
        return;
    }

    // ================= consumer warps =================
    const int warp  = tid >> 5;
    const int warpM = warp >> 1;     // 0..3, 32 rows each
    const int warpN = warp & 1;      // 0..1, 64 cols each

    float c[2][8][4];
#pragma unroll
    for (int i = 0; i < 2; ++i)
#pragma unroll
        for (int j = 0; j < 8; ++j)
#pragma unroll
            for (int k = 0; k < 4; ++k) c[i][j][k] = 0.0f;

    // per-lane swizzled ldmatrix base offsets (swizzle invariant under row+16 => +2048B)
    const int lrow = lane & 15;
    const int csel = lane >> 4;
    uint32_t offA0[4], offB0[4];
    {
        const int rA = warpM * 32 + lrow;
        const int rB = warpN * 64 + lrow;
#pragma unroll
        for (int kk = 0; kk < 4; ++kk) {
            offA0[kk] = sw_off(rA, (kk << 1) | csel);
            offB0[kk] = sw_off(rB, (kk << 1) | csel);
        }
    }

    int s = 0, ph = 0;
    for (int kt = 0; kt < KT_HALF; ++kt) {
        const uint32_t a_s = sb + SMEM_HDR + s * STAGE_B;
        const uint32_t b_s = a_s + A_STAGE_B;

        mbar_wait(FULL + 8u * s, (uint32_t)ph);

#pragma unroll
        for (int kk = 0; kk < 4; ++kk) {
            uint32_t a[2][4], b[4][4];
            ldsm4(a[0], a_s + offA0[kk]);
            ldsm4(a[1], a_s + offA0[kk] + 2048);
#pragma unroll
            for (int q = 0; q < 4; ++q)
                ldsm4(b[q], b_s + offB0[kk] + (uint32_t)(q * 2048));
#pragma unroll
            for (int q = 0; q < 4; ++q) {
                mma16816(c[0][2 * q + 0], a[0], b[q][0], b[q][2]);
                mma16816(c[0][2 * q + 1], a[0], b[q][1], b[q][3]);
                mma16816(c[1][2 * q + 0], a[1], b[q][0], b[q][2]);
                mma16816(c[1][2 * q + 1], a[1], b[q][1], b[q][3]);
            }
        }

        mbar_arrive(EMPTY + 8u * s);
        if (++s == STAGES) { s = 0; ph ^= 1; }
    }

    // ---- split-K combine + fused epilogue ----
    const int mBase = tileM * BM + warpM * 32 + (lane >> 2);
    const int nBase = tileN * BN + warpN * 64 + (lane & 3) * 2;

    if (ks == 0) {
        // half-0: store raw partials, fence, set flag
#pragma unroll
        for (int mt = 0; mt < 2; ++mt) {
#pragma unroll
            for (int nt = 0; nt < 8; ++nt) {
#pragma unroll
                for (int half = 0; half < 2; ++half) {
                    const int m = mBase + mt * 16 + half * 8;
                    const int n = nBase + nt * 8;
                    const size_t off = (size_t)m * NDIM + n;
                    float2 p;
                    p.x = c[mt][nt][2 * half + 0];
                    p.y = c[mt][nt][2 * half + 1];
                    *reinterpret_cast<float2*>(g_part + off) = p;
                }
            }
        }
        __syncthreads();           // all consumer partials stored (producer exited)
        if (tid == 0) {
            __threadfence();       // order partial stores before flag
            atomicExch(&g_flag[tile], 1);
        }
    } else {
        // half-1: wait for partner's partials, combine, epilogue
        if (tid == 0) {
            while (atomicAdd(&g_flag[tile], 0) == 0) { __nanosleep(64); }
            __threadfence();       // acquire: order subsequent loads
        }
        __syncthreads();
#pragma unroll
        for (int mt = 0; mt < 2; ++mt) {
#pragma unroll
            for (int nt = 0; nt < 8; ++nt) {
#pragma unroll
                for (int half = 0; half < 2; ++half) {
                    const int m = mBase + mt * 16 + half * 8;
                    const int n = nBase + nt * 8;
                    const size_t off = (size_t)m * NDIM + n;
                    float2 pp = *reinterpret_cast<const float2*>(g_part + off);
                    float2 nz = *reinterpret_cast<const float2*>(noise + off);
                    float2 bd = *reinterpret_cast<const float2*>(g_badd + n);
                    float accx = c[mt][nt][2 * half + 0] + pp.x;   // exact int add
                    float accy = c[mt][nt][2 * half + 1] + pp.y;
                    float2 o;
                    o.x = fmaf(accx, INVSCALE, fmaf(0.01f, nz.x, bd.x));
                    o.y = fmaf(accy, INVSCALE, fmaf(0.01f, nz.y, bd.y));
                    *reinterpret_cast<float2*>(out + off) = o;
                }
            }
        }
    }
}

// ---------------- launch ----------------
typedef CUresult (*PFN_tmEncode)(
    CUtensorMap*, CUtensorMapDataType, cuuint32_t, void*,
    const cuuint64_t*, const cuuint64_t*, const cuuint32_t*, const cuuint32_t*,
    CUtensorMapInterleave, CUtensorMapSwizzle, CUtensorMapL2promotion,
    CUtensorMapFloatOOBfill);

extern "C" void kernel_launch(void* const* d_in, const int* in_sizes, int n_in,
                              void* d_out, int out_size) {
    const float* x  = (const float*)d_in[0];   // tensor  [4096,4096]
    const float* w  = (const float*)d_in[1];   // weights [4096,4096]
    const float* b  = (const float*)d_in[2];   // biases  [4096]
    const float* nz = (const float*)d_in[3];   // noise   [4096,4096]
    float* out = (float*)d_out;

    const int qgrid = (NDIM * NDIM / 4) / 256;  // 16384
    quant_kernel<<<qgrid, 256>>>((const float4*)x, 0, 4.0f, 31.75f);
    quant_kernel<<<qgrid, 256>>>((const float4*)w, 1, 1.0f, 127.0f);
    quant_bias_kernel<<<NDIM / 256, 256>>>(b);
    flag_clear_kernel<<<NTILES / 256, 256>>>();

    // build tensormaps (host-side, pure; no allocation)
    void* encFn = nullptr;
    cudaDriverEntryPointQueryResult qres;
    cudaGetDriverEntryPoint("cuTensorMapEncodeTiled", &encFn, cudaEnableDefault, &qres);
    PFN_tmEncode enc = (PFN_tmEncode)encFn;

    void *xq_ptr = nullptr, *wq_ptr = nullptr;
    cudaGetSymbolAddress(&xq_ptr, g_Xq);
    cudaGetSymbolAddress(&wq_ptr, g_Wq);

    cuuint64_t dims[2]    = {(cuuint64_t)NDIM, (cuuint64_t)NDIM};
    cuuint64_t strides[1] = {(cuuint64_t)NDIM * 2};
    cuuint32_t box[2]     = {(cuuint32_t)BK, (cuuint32_t)BM};   // 64 elems x 128 rows
    cuuint32_t estr[2]    = {1, 1};

    CUtensorMap tmA, tmB;
    enc(&tmA, CU_TENSOR_MAP_DATA_TYPE_BFLOAT16, 2, xq_ptr, dims, strides, box, estr,
        CU_TENSOR_MAP_INTERLEAVE_NONE, CU_TENSOR_MAP_SWIZZLE_128B,
        CU_TENSOR_MAP_L2_PROMOTION_L2_128B, CU_TENSOR_MAP_FLOAT_OOB_FILL_NONE);
    enc(&tmB, CU_TENSOR_MAP_DATA_TYPE_BFLOAT16, 2, wq_ptr, dims, strides, box, estr,
        CU_TENSOR_MAP_INTERLEAVE_NONE, CU_TENSOR_MAP_SWIZZLE_128B,
        CU_TENSOR_MAP_L2_PROMOTION_L2_128B, CU_TENSOR_MAP_FLOAT_OOB_FILL_NONE);

    cudaFuncSetAttribute(gemm_kernel, cudaFuncAttributeMaxDynamicSharedMemorySize, SMEM_TOTAL);
    gemm_kernel<<<NTILES * KSPLIT, 288, SMEM_TOTAL>>>(tmA, tmB, nz, out);
}

// round 12
// speedup vs baseline: 1.6125x; 1.0187x over previous
#include <cuda_runtime.h>
#include <cuda.h>
#include <cuda_bf16.h>
#include <stdint.h>

#define DI __device__ __forceinline__

// ---------------- problem constants ----------------
static constexpr int    NDIM     = 4096;
static constexpr float  INVSCALE = 1.0f / (31.75f * 127.0f);   // 1/(sx*sw)

// ---------------- GEMM tiling (bf16 HMMA + TMA, warp-specialized, hybrid split-K) ----------------
static constexpr int BM = 128, BN = 128, BK = 64;
static constexpr int STAGES = 3;
static constexpr int KT = NDIM / BK;                    // 64 k-iterations full
static constexpr int A_STAGE_B = BM * 128;              // 16384 (128 rows x 128B)
static constexpr int B_STAGE_B = BN * 128;              // 16384
static constexpr int STAGE_B   = A_STAGE_B + B_STAGE_B; // 32768
static constexpr int SMEM_HDR  = 1024;
static constexpr int SMEM_TOTAL = SMEM_HDR + STAGES * STAGE_B;  // 99328
static constexpr int NCONS = 256;                       // consumer threads
static constexpr int NTILES = (NDIM / BM) * (NDIM / BN);        // 1024
static constexpr int FULL_TILES = 888;                  // 3 x 296 — perfectly packed waves
static constexpr int SPLIT_TILES = NTILES - FULL_TILES; // 136 tiles, split-K=2
static constexpr int GRID = FULL_TILES + 2 * SPLIT_TILES;       // 1160 CTAs

// ---------------- device scratch (allocation-free rule) ----------------
__device__ __nv_bfloat16 g_Xq[(size_t)NDIM * NDIM];   // quantized activations (integer-valued bf16)
__device__ __nv_bfloat16 g_Wq[(size_t)NDIM * NDIM];   // quantized weights (integer-valued bf16)
__device__ float         g_badd[NDIM];                // epilogue bias term
__device__ float         g_part[(size_t)SPLIT_TILES * BM * BN]; // split-K partials
__device__ int           g_flag[SPLIT_TILES];         // half-0 completion flags

// ---------------- PTX helpers ----------------
DI uint32_t smem_u32(const void* p) {
    uint32_t a;
    asm("{ .reg .u64 t; cvta.to.shared.u64 t, %1; cvt.u32.u64 %0, t; }" : "=r"(a) : "l"(p));
    return a;
}
DI void ldsm4(uint32_t* r, uint32_t addr) {
    asm volatile("ldmatrix.sync.aligned.m8n8.x4.shared.b16 {%0,%1,%2,%3}, [%4];"
                 : "=r"(r[0]), "=r"(r[1]), "=r"(r[2]), "=r"(r[3]) : "r"(addr));
}
DI void mma16816(float* c, const uint32_t* a, uint32_t b0, uint32_t b1) {
    asm volatile(
        "mma.sync.aligned.m16n8k16.row.col.f32.bf16.bf16.f32 "
        "{%0,%1,%2,%3}, {%4,%5,%6,%7}, {%8,%9}, {%0,%1,%2,%3};"
        : "+f"(c[0]), "+f"(c[1]), "+f"(c[2]), "+f"(c[3])
        : "r"(a[0]), "r"(a[1]), "r"(a[2]), "r"(a[3]), "r"(b0), "r"(b1));
}
// SW128 swizzled byte offset: 128B rows, 16B chunk c in [0,8)
DI uint32_t sw_off(int row, int c) {
    return (uint32_t)(row * 128 + ((c ^ (row & 7)) << 4));
}
DI void mbar_init(uint32_t a, uint32_t cnt) {
    asm volatile("mbarrier.init.shared.b64 [%0], %1;" :: "r"(a), "r"(cnt) : "memory");
}
DI void mbar_expect(uint32_t a, uint32_t bytes) {
    asm volatile("mbarrier.arrive.expect_tx.shared.b64 _, [%0], %1;"
                 :: "r"(a), "r"(bytes) : "memory");
}
DI void mbar_arrive(uint32_t a) {
    asm volatile("mbarrier.arrive.shared.b64 _, [%0];" :: "r"(a) : "memory");
}
DI void mbar_wait(uint32_t a, uint32_t parity) {
    asm volatile(
        "{\n\t.reg .pred P;\n"
        "WL_%=:\n\t"
        "mbarrier.try_wait.parity.acquire.cta.shared::cta.b64 P, [%0], %1, 0x989680;\n\t"
        "@P bra WD_%=;\n\t"
        "bra WL_%=;\n"
        "WD_%=:\n\t}"
        :: "r"(a), "r"(parity) : "memory");
}
DI void tma2d(uint32_t dst, const CUtensorMap* tm, int cx, int cy, uint32_t mbar) {
    asm volatile(
        "cp.async.bulk.tensor.2d.shared::cluster.global.tile.mbarrier::complete_tx::bytes "
        "[%0], [%1, {%2, %3}], [%4];"
        :: "r"(dst), "l"(tm), "r"(cx), "r"(cy), "r"(mbar) : "memory");
}

// ---------------- quantize kernels ----------------
__global__ void quant_kernel(const float4* __restrict__ src, int which,
                             float clip, float scale) {
    size_t i = (size_t)blockIdx.x * blockDim.x + threadIdx.x;
    float4 v = src[i];
    float a0 = rintf(fminf(clip, fmaxf(-clip, v.x)) * scale);
    float a1 = rintf(fminf(clip, fmaxf(-clip, v.y)) * scale);
    float a2 = rintf(fminf(clip, fmaxf(-clip, v.z)) * scale);
    float a3 = rintf(fminf(clip, fmaxf(-clip, v.w)) * scale);
    __nv_bfloat162 p0 = __floats2bfloat162_rn(a0, a1);
    __nv_bfloat162 p1 = __floats2bfloat162_rn(a2, a3);
    uint2 o;
    o.x = *reinterpret_cast<uint32_t*>(&p0);
    o.y = *reinterpret_cast<uint32_t*>(&p1);
    uint2* dst = reinterpret_cast<uint2*>(which ? g_Wq : g_Xq);
    dst[i] = o;
}

__global__ void quant_bias_kernel(const float* __restrict__ b) {
    int i = blockIdx.x * blockDim.x + threadIdx.x;
    float q = rintf(fminf(1.0f, fmaxf(-1.0f, b[i])) * 127.0f);
    g_badd[i] = 32.0f * q * INVSCALE;   // quantized ones-column (=32) * quantized bias
    if (i < SPLIT_TILES) g_flag[i] = 0; // fold flag clearing into this pass
}

// ---------------- GEMM: producer warp (TMA) + 8 consumer warps (HMMA), hybrid split-K ----------------
__global__ __launch_bounds__(288, 2)
void gemm_kernel(const __grid_constant__ CUtensorMap tmA,
                 const __grid_constant__ CUtensorMap tmB,
                 const float* __restrict__ noise, float* __restrict__ out) {
    extern __shared__ __align__(1024) char smem[];
    const uint32_t sb = smem_u32(smem);
    const int tid  = threadIdx.x;
    const int lane = tid & 31;

    // ---- tile / split mapping ----
    const int bid = blockIdx.x;
    int tile, ks, ktcnt, kbase;
    if (bid < FULL_TILES) {
        tile = bid; ks = 0; ktcnt = KT; kbase = 0;
    } else {
        const int j = bid - FULL_TILES;
        tile = FULL_TILES + (j >> 1);
        ks = j & 1;
        ktcnt = KT / 2;                 // 32
        kbase = ks * (KT / 2);
    }
    const int tileM = tile >> 5;
    const int tileN = tile & 31;
    const bool is_split = (bid >= FULL_TILES);

    const uint32_t FULL  = sb;       // full[s]  at sb + 8*s
    const uint32_t EMPTY = sb + 24;  // empty[s] at sb + 24 + 8*s

    if (tid == 0) {
#pragma unroll
        for (int s = 0; s < STAGES; ++s) {
            mbar_init(FULL + 8u * s, 1);
            mbar_init(EMPTY + 8u * s, NCONS);
        }
        asm volatile("fence.mbarrier_init.release.cluster;" ::: "memory");
    }
    __syncthreads();

    if (tid >= NCONS) {
        // ================= producer warp (lane 0 only) =================
        if (lane == 0) {
#pragma unroll
            for (int i = 0; i < STAGES; ++i) {
                const uint32_t a_s = sb + SMEM_HDR + i * STAGE_B;
                mbar_expect(FULL + 8u * i, (uint32_t)STAGE_B);
                tma2d(a_s,             &tmA, (kbase + i) * BK, tileM * BM, FULL + 8u * i);
                tma2d(a_s + A_STAGE_B, &tmB, (kbase + i) * BK, tileN * BN, FULL + 8u * i);
            }
            int s = 0, php = 0;
            for (int f = STAGES; f < ktcnt; ++f) {
                const uint32_t a_s = sb + SMEM_HDR + s * STAGE_B;
                mbar_wait(EMPTY + 8u * s, (uint32_t)php);
                mbar_expect(FULL + 8u * s, (uint32_t)STAGE_B);
                tma2d(a_s,             &tmA, (kbase + f) * BK, tileM * BM, FULL + 8u * s);
                tma2d(a_s + A_STAGE_B, &tmB, (kbase + f) * BK, tileN * BN, FULL + 8u * s);
                if (++s == STAGES) { s = 0; php ^= 1; }
            }
        }
        return;
    }

    // ================= consumer warps =================
    const int warp  = tid >> 5;
    const int warpM = warp >> 1;     // 0..3, 32 rows each
    const int warpN = warp & 1;      // 0..1, 64 cols each

    float c[2][8][4];
#pragma unroll
    for (int i = 0; i < 2; ++i)
#pragma unroll
        for (int j = 0; j < 8; ++j)
#pragma unroll
            for (int k = 0; k < 4; ++k) c[i][j][k] = 0.0f;

    // per-lane swizzled ldmatrix base offsets (swizzle invariant under row+16 => +2048B)
    const int lrow = lane & 15;
    const int csel = lane >> 4;
    uint32_t offA0[4], offB0[4];
    {
        const int rA = warpM * 32 + lrow;
        const int rB = warpN * 64 + lrow;
#pragma unroll
        for (int kk = 0; kk < 4; ++kk) {
            offA0[kk] = sw_off(rA, (kk << 1) | csel);
            offB0[kk] = sw_off(rB, (kk << 1) | csel);
        }
    }

    int s = 0, ph = 0;
    for (int kt = 0; kt < ktcnt; ++kt) {
        const uint32_t a_s = sb + SMEM_HDR + s * STAGE_B;
        const uint32_t b_s = a_s + A_STAGE_B;

        mbar_wait(FULL + 8u * s, (uint32_t)ph);

#pragma unroll
        for (int kk = 0; kk < 4; ++kk) {
            uint32_t a[2][4], b[4][4];
            ldsm4(a[0], a_s + offA0[kk]);
            ldsm4(a[1], a_s + offA0[kk] + 2048);
#pragma unroll
            for (int q = 0; q < 4; ++q)
                ldsm4(b[q], b_s + offB0[kk] + (uint32_t)(q * 2048));
#pragma unroll
            for (int q = 0; q < 4; ++q) {
                mma16816(c[0][2 * q + 0], a[0], b[q][0], b[q][2]);
                mma16816(c[0][2 * q + 1], a[0], b[q][1], b[q][3]);
                mma16816(c[1][2 * q + 0], a[1], b[q][0], b[q][2]);
                mma16816(c[1][2 * q + 1], a[1], b[q][1], b[q][3]);
            }
        }

        mbar_arrive(EMPTY + 8u * s);
        if (++s == STAGES) { s = 0; ph ^= 1; }
    }

    // ---- epilogue ----
    const int mLoc0 = warpM * 32 + (lane >> 2);
    const int nLoc0 = warpN * 64 + (lane & 3) * 2;
    const int mBase = tileM * BM + mLoc0;
    const int nBase = tileN * BN + nLoc0;

    if (!is_split) {
        // full tile: direct fused epilogue
#pragma unroll
        for (int mt = 0; mt < 2; ++mt) {
#pragma unroll
            for (int nt = 0; nt < 8; ++nt) {
#pragma unroll
                for (int half = 0; half < 2; ++half) {
                    const int m = mBase + mt * 16 + half * 8;
                    const int n = nBase + nt * 8;
                    const size_t off = (size_t)m * NDIM + n;
                    float2 nz = *reinterpret_cast<const float2*>(noise + off);
                    float2 bd = *reinterpret_cast<const float2*>(g_badd + n);
                    float2 o;
                    o.x = fmaf(c[mt][nt][2 * half + 0], INVSCALE, fmaf(0.01f, nz.x, bd.x));
                    o.y = fmaf(c[mt][nt][2 * half + 1], INVSCALE, fmaf(0.01f, nz.y, bd.y));
                    *reinterpret_cast<float2*>(out + off) = o;
                }
            }
        }
        return;
    }

    // split tile: combine via partials scratch
    const int sidx = tile - FULL_TILES;
    float* part = g_part + (size_t)sidx * BM * BN;

    if (ks == 0) {
        // half-0: store raw partials, fence, set flag
#pragma unroll
        for (int mt = 0; mt < 2; ++mt) {
#pragma unroll
            for (int nt = 0; nt < 8; ++nt) {
#pragma unroll
                for (int half = 0; half < 2; ++half) {
                    const int mL = mLoc0 + mt * 16 + half * 8;
                    const int nL = nLoc0 + nt * 8;
                    float2 p;
                    p.x = c[mt][nt][2 * half + 0];
                    p.y = c[mt][nt][2 * half + 1];
                    *reinterpret_cast<float2*>(part + mL * BN + nL) = p;
                }
            }
        }
        __syncthreads();           // consumer partials all stored (producer exited)
        if (tid == 0) {
            __threadfence();       // order partial stores before flag
            atomicExch(&g_flag[sidx], 1);
        }
    } else {
        // half-1: wait for partner's partials, combine, fused epilogue
        if (tid == 0) {
            while (atomicAdd(&g_flag[sidx], 0) == 0) { __nanosleep(64); }
            __threadfence();
        }
        __syncthreads();
#pragma unroll
        for (int mt = 0; mt < 2; ++mt) {
#pragma unroll
            for (int nt = 0; nt < 8; ++nt) {
#pragma unroll
                for (int half = 0; half < 2; ++half) {
                    const int mL = mLoc0 + mt * 16 + half * 8;
                    const int nL = nLoc0 + nt * 8;
                    const int m = tileM * BM + mL;
                    const int n = tileN * BN + nL;
                    const size_t off = (size_t)m * NDIM + n;
                    float2 pp = *reinterpret_cast<const float2*>(part + mL * BN + nL);
                    float2 nz = *reinterpret_cast<const float2*>(noise + off);
                    float2 bd = *reinterpret_cast<const float2*>(g_badd + n);
                    float accx = c[mt][nt][2 * half + 0] + pp.x;   // exact int add
                    float accy = c[mt][nt][2 * half + 1] + pp.y;
                    float2 o;
                    o.x = fmaf(accx, INVSCALE, fmaf(0.01f, nz.x, bd.x));
                    o.y = fmaf(accy, INVSCALE, fmaf(0.01f, nz.y, bd.y));
                    *reinterpret_cast<float2*>(out + off) = o;
                }
            }
        }
    }
}

// ---------------- launch ----------------
typedef CUresult (*PFN_tmEncode)(
    CUtensorMap*, CUtensorMapDataType, cuuint32_t, void*,
    const cuuint64_t*, const cuuint64_t*, const cuuint32_t*, const cuuint32_t*,
    CUtensorMapInterleave, CUtensorMapSwizzle, CUtensorMapL2promotion,
    CUtensorMapFloatOOBfill);

extern "C" void kernel_launch(void* const* d_in, const int* in_sizes, int n_in,
                              void* d_out, int out_size) {
    const float* x  = (const float*)d_in[0];   // tensor  [4096,4096]
    const float* w  = (const float*)d_in[1];   // weights [4096,4096]
    const float* b  = (const float*)d_in[2];   // biases  [4096]
    const float* nz = (const float*)d_in[3];   // noise   [4096,4096]
    float* out = (float*)d_out;

    const int qgrid = (NDIM * NDIM / 4) / 256;  // 16384
    quant_kernel<<<qgrid, 256>>>((const float4*)x, 0, 4.0f, 31.75f);
    quant_kernel<<<qgrid, 256>>>((const float4*)w, 1, 1.0f, 127.0f);
    quant_bias_kernel<<<NDIM / 256, 256>>>(b);

    // build tensormaps (host-side, pure; no allocation)
    void* encFn = nullptr;
    cudaDriverEntryPointQueryResult qres;
    cudaGetDriverEntryPoint("cuTensorMapEncodeTiled", &encFn, cudaEnableDefault, &qres);
    PFN_tmEncode enc = (PFN_tmEncode)encFn;

    void *xq_ptr = nullptr, *wq_ptr = nullptr;
    cudaGetSymbolAddress(&xq_ptr, g_Xq);
    cudaGetSymbolAddress(&wq_ptr, g_Wq);

    cuuint64_t dims[2]    = {(cuuint64_t)NDIM, (cuuint64_t)NDIM};
    cuuint64_t strides[1] = {(cuuint64_t)NDIM * 2};
    cuuint32_t box[2]     = {(cuuint32_t)BK, (cuuint32_t)BM};   // 64 elems x 128 rows
    cuuint32_t estr[2]    = {1, 1};

    CUtensorMap tmA, tmB;
    enc(&tmA, CU_TENSOR_MAP_DATA_TYPE_BFLOAT16, 2, xq_ptr, dims, strides, box, estr,
        CU_TENSOR_MAP_INTERLEAVE_NONE, CU_TENSOR_MAP_SWIZZLE_128B,
        CU_TENSOR_MAP_L2_PROMOTION_L2_128B, CU_TENSOR_MAP_FLOAT_OOB_FILL_NONE);
    enc(&tmB, CU_TENSOR_MAP_DATA_TYPE_BFLOAT16, 2, wq_ptr, dims, strides, box, estr,
        CU_TENSOR_MAP_INTERLEAVE_NONE, CU_TENSOR_MAP_SWIZZLE_128B,
        CU_TENSOR_MAP_L2_PROMOTION_L2_128B, CU_TENSOR_MAP_FLOAT_OOB_FILL_NONE);

    cudaFuncSetAttribute(gemm_kernel, cudaFuncAttributeMaxDynamicSharedMemorySize, SMEM_TOTAL);
    gemm_kernel<<<GRID, 288, SMEM_TOTAL>>>(tmA, tmB, nz, out);
}

// round 13
// speedup vs baseline: 1.6858x; 1.0454x over previous
#include <cuda_runtime.h>
#include <cuda.h>
#include <cuda_bf16.h>
#include <stdint.h>

#define DI __device__ __forceinline__

// ---------------- problem constants ----------------
static constexpr int    NDIM     = 4096;
static constexpr float  INVSCALE = 1.0f / (31.75f * 127.0f);   // 1/(sx*sw)

// ---------------- GEMM tiling (bf16 HMMA + TMA, warp-specialized) ----------------
static constexpr int BM = 128, BN = 128, BK = 64;
static constexpr int STAGES = 3;
static constexpr int KT = NDIM / BK;                    // 64 k-iterations
static constexpr int A_STAGE_B = BM * 128;              // 16384 (128 rows x 128B)
static constexpr int B_STAGE_B = BN * 128;              // 16384
static constexpr int STAGE_B   = A_STAGE_B + B_STAGE_B; // 32768
static constexpr int SMEM_HDR  = 1024;
static constexpr int SMEM_TOTAL = SMEM_HDR + STAGES * STAGE_B;  // 99328
static constexpr int NCONS = 256;                       // consumer threads

// ---------------- device scratch (allocation-free rule) ----------------
__device__ __nv_bfloat16 g_Xq[(size_t)NDIM * NDIM];   // quantized activations (integer-valued bf16)
__device__ __nv_bfloat16 g_Wq[(size_t)NDIM * NDIM];   // quantized weights (integer-valued bf16)
__device__ float         g_badd[NDIM];                // epilogue bias term

// ---------------- PTX helpers ----------------
DI uint32_t smem_u32(const void* p) {
    uint32_t a;
    asm("{ .reg .u64 t; cvta.to.shared.u64 t, %1; cvt.u32.u64 %0, t; }" : "=r"(a) : "l"(p));
    return a;
}
DI void ldsm4(uint32_t* r, uint32_t addr) {
    asm volatile("ldmatrix.sync.aligned.m8n8.x4.shared.b16 {%0,%1,%2,%3}, [%4];"
                 : "=r"(r[0]), "=r"(r[1]), "=r"(r[2]), "=r"(r[3]) : "r"(addr));
}
DI void mma16816(float* c, const uint32_t* a, uint32_t b0, uint32_t b1) {
    asm volatile(
        "mma.sync.aligned.m16n8k16.row.col.f32.bf16.bf16.f32 "
        "{%0,%1,%2,%3}, {%4,%5,%6,%7}, {%8,%9}, {%0,%1,%2,%3};"
        : "+f"(c[0]), "+f"(c[1]), "+f"(c[2]), "+f"(c[3])
        : "r"(a[0]), "r"(a[1]), "r"(a[2]), "r"(a[3]), "r"(b0), "r"(b1));
}
// SW128 swizzled byte offset: 128B rows, 16B chunk c in [0,8)
DI uint32_t sw_off(int row, int c) {
    return (uint32_t)(row * 128 + ((c ^ (row & 7)) << 4));
}
DI void mbar_init(uint32_t a, uint32_t cnt) {
    asm volatile("mbarrier.init.shared.b64 [%0], %1;" :: "r"(a), "r"(cnt) : "memory");
}
DI void mbar_expect(uint32_t a, uint32_t bytes) {
    asm volatile("mbarrier.arrive.expect_tx.shared.b64 _, [%0], %1;"
                 :: "r"(a), "r"(bytes) : "memory");
}
DI void mbar_arrive_rel(uint32_t a) {
    asm volatile("mbarrier.arrive.release.cta.shared::cta.b64 _, [%0];" :: "r"(a) : "memory");
}
DI void mbar_wait(uint32_t a, uint32_t parity) {
    asm volatile(
        "{\n\t.reg .pred P;\n"
        "WL_%=:\n\t"
        "mbarrier.try_wait.parity.acquire.cta.shared::cta.b64 P, [%0], %1, 0x989680;\n\t"
        "@P bra WD_%=;\n\t"
        "bra WL_%=;\n"
        "WD_%=:\n\t}"
        :: "r"(a), "r"(parity) : "memory");
}
DI void tma2d(uint32_t dst, const CUtensorMap* tm, int cx, int cy, uint32_t mbar) {
    asm volatile(
        "cp.async.bulk.tensor.2d.shared::cluster.global.tile.mbarrier::complete_tx::bytes "
        "[%0], [%1, {%2, %3}], [%4];"
        :: "r"(dst), "l"(tm), "r"(cx), "r"(cy), "r"(mbar) : "memory");
}

// ---------------- fused quantize kernel (X and W in one launch) ----------------
// 16 floats per thread: 4x float4 loads, 1x uint4 store. blockIdx.y: 0 = X, 1 = W.
__global__ void quant_both_kernel(const float4* __restrict__ x,
                                  const float4* __restrict__ w) {
    const int which = blockIdx.y;
    const float clip  = which ? 1.0f   : 4.0f;
    const float scale = which ? 127.0f : 31.75f;
    const float4* src = which ? w : x;
    size_t i = (size_t)blockIdx.x * blockDim.x + threadIdx.x;

    uint32_t words[8];
#pragma unroll
    for (int j = 0; j < 4; ++j) {
        float4 v = src[i * 4 + j];
        float a0 = rintf(fminf(clip, fmaxf(-clip, v.x)) * scale);
        float a1 = rintf(fminf(clip, fmaxf(-clip, v.y)) * scale);
        float a2 = rintf(fminf(clip, fmaxf(-clip, v.z)) * scale);
        float a3 = rintf(fminf(clip, fmaxf(-clip, v.w)) * scale);
        __nv_bfloat162 p0 = __floats2bfloat162_rn(a0, a1);
        __nv_bfloat162 p1 = __floats2bfloat162_rn(a2, a3);
        words[2 * j + 0] = *reinterpret_cast<uint32_t*>(&p0);
        words[2 * j + 1] = *reinterpret_cast<uint32_t*>(&p1);
    }
    uint4* dst = reinterpret_cast<uint4*>(which ? g_Wq : g_Xq);
    dst[i * 2 + 0] = make_uint4(words[0], words[1], words[2], words[3]);
    dst[i * 2 + 1] = make_uint4(words[4], words[5], words[6], words[7]);
}

__global__ void quant_bias_kernel(const float* __restrict__ b) {
    int i = blockIdx.x * blockDim.x + threadIdx.x;
    float q = rintf(fminf(1.0f, fmaxf(-1.0f, b[i])) * 127.0f);
    g_badd[i] = 32.0f * q * INVSCALE;   // quantized ones-column (=32) * quantized bias
}

// ---------------- GEMM: producer warp (TMA) + 8 consumer warps (HMMA) ----------------
__global__ __launch_bounds__(288, 2)
void gemm_kernel(const __grid_constant__ CUtensorMap tmA,
                 const __grid_constant__ CUtensorMap tmB,
                 const float* __restrict__ noise, float* __restrict__ out) {
    extern __shared__ __align__(1024) char smem[];
    const uint32_t sb = smem_u32(smem);
    const int tid  = threadIdx.x;
    const int lane = tid & 31;

    const uint32_t FULL  = sb;       // full[s]  at sb + 8*s
    const uint32_t EMPTY = sb + 24;  // empty[s] at sb + 24 + 8*s

    if (tid == 0) {
#pragma unroll
        for (int s = 0; s < STAGES; ++s) {
            mbar_init(FULL + 8u * s, 1);
            mbar_init(EMPTY + 8u * s, NCONS);
        }
        asm volatile("fence.mbarrier_init.release.cluster;" ::: "memory");
    }
    __syncthreads();

    const int tileM = blockIdx.y, tileN = blockIdx.x;

    if (tid >= NCONS) {
        // ================= producer warp (lane 0 only) =================
        if (lane == 0) {
#pragma unroll
            for (int f = 0; f < STAGES; ++f) {
                const uint32_t a_s = sb + SMEM_HDR + f * STAGE_B;
                mbar_expect(FULL + 8u * f, (uint32_t)STAGE_B);
                tma2d(a_s,             &tmA, f * BK, tileM * BM, FULL + 8u * f);
                tma2d(a_s + A_STAGE_B, &tmB, f * BK, tileN * BN, FULL + 8u * f);
            }
            int s = 0, php = 0;
            for (int f = STAGES; f < KT; ++f) {
                const uint32_t a_s = sb + SMEM_HDR + s * STAGE_B;
                mbar_wait(EMPTY + 8u * s, (uint32_t)php);
                mbar_expect(FULL + 8u * s, (uint32_t)STAGE_B);
                tma2d(a_s,             &tmA, f * BK, tileM * BM, FULL + 8u * s);
                tma2d(a_s + A_STAGE_B, &tmB, f * BK, tileN * BN, FULL + 8u * s);
                if (++s == STAGES) { s = 0; php ^= 1; }
            }
        }
        return;
    }

    // ================= consumer warps =================
    const int warp  = tid >> 5;
    const int warpM = warp >> 1;     // 0..3, 32 rows each
    const int warpN = warp & 1;      // 0..1, 64 cols each

    float c[2][8][4];
#pragma unroll
    for (int i = 0; i < 2; ++i)
#pragma unroll
        for (int j = 0; j < 8; ++j)
#pragma unroll
            for (int k = 0; k < 4; ++k) c[i][j][k] = 0.0f;

    // per-lane swizzled ldmatrix base offsets (swizzle invariant under row+16 => +2048B)
    const int lrow = lane & 15;
    const int csel = lane >> 4;
    uint32_t offA0[4], offB0[4];
    {
        const int rA = warpM * 32 + lrow;
        const int rB = warpN * 64 + lrow;
#pragma unroll
        for (int kk = 0; kk < 4; ++kk) {
            offA0[kk] = sw_off(rA, (kk << 1) | csel);
            offB0[kk] = sw_off(rB, (kk << 1) | csel);
        }
    }

    int s = 0, ph = 0;
    for (int kt = 0; kt < KT; ++kt) {
        const uint32_t a_s = sb + SMEM_HDR + s * STAGE_B;
        const uint32_t b_s = a_s + A_STAGE_B;

        mbar_wait(FULL + 8u * s, (uint32_t)ph);

#pragma unroll
        for (int kk = 0; kk < 4; ++kk) {
            uint32_t a[2][4], b[4][4];
            ldsm4(a[0], a_s + offA0[kk]);
            ldsm4(a[1], a_s + offA0[kk] + 2048);
#pragma unroll
            for (int q = 0; q < 4; ++q)
                ldsm4(b[q], b_s + offB0[kk] + (uint32_t)(q * 2048));
            // all smem reads of this stage have been issued after kk==3's burst;
            // release-arrive orders them before the producer's TMA overwrite.
            if (kk == 3) mbar_arrive_rel(EMPTY + 8u * s);
#pragma unroll
            for (int q = 0; q < 4; ++q) {
                mma16816(c[0][2 * q + 0], a[0], b[q][0], b[q][2]);
                mma16816(c[0][2 * q + 1], a[0], b[q][1], b[q][3]);
                mma16816(c[1][2 * q + 0], a[1], b[q][0], b[q][2]);
                mma16816(c[1][2 * q + 1], a[1], b[q][1], b[q][3]);
            }
        }

        if (++s == STAGES) { s = 0; ph ^= 1; }
    }

    // ---- fused epilogue: out = acc*INV + badd[n] + 0.01*noise ----
    const int mBase = tileM * BM + warpM * 32 + (lane >> 2);
    const int nBase = tileN * BN + warpN * 64 + (lane & 3) * 2;
#pragma unroll
    for (int mt = 0; mt < 2; ++mt) {
#pragma unroll
        for (int nt = 0; nt < 8; ++nt) {
#pragma unroll
            for (int half = 0; half < 2; ++half) {
                const int m = mBase + mt * 16 + half * 8;
                const int n = nBase + nt * 8;
                const size_t off = (size_t)m * NDIM + n;
                float2 nz = *reinterpret_cast<const float2*>(noise + off);
                float2 bd = *reinterpret_cast<const float2*>(g_badd + n);
                float2 o;
                o.x = fmaf(c[mt][nt][2 * half + 0], INVSCALE, fmaf(0.01f, nz.x, bd.x));
                o.y = fmaf(c[mt][nt][2 * half + 1], INVSCALE, fmaf(0.01f, nz.y, bd.y));
                *reinterpret_cast<float2*>(out + off) = o;
            }
        }
    }
}

// ---------------- launch ----------------
typedef CUresult (*PFN_tmEncode)(
    CUtensorMap*, CUtensorMapDataType, cuuint32_t, void*,
    const cuuint64_t*, const cuuint64_t*, const cuuint32_t*, const cuuint32_t*,
    CUtensorMapInterleave, CUtensorMapSwizzle, CUtensorMapL2promotion,
    CUtensorMapFloatOOBfill);

extern "C" void kernel_launch(void* const* d_in, const int* in_sizes, int n_in,
                              void* d_out, int out_size) {
    const float* x  = (const float*)d_in[0];   // tensor  [4096,4096]
    const float* w  = (const float*)d_in[1];   // weights [4096,4096]
    const float* b  = (const float*)d_in[2];   // biases  [4096]
    const float* nz = (const float*)d_in[3];   // noise   [4096,4096]
    float* out = (float*)d_out;

    // fused quantization: 16 floats per thread
    dim3 qgrid((NDIM * NDIM / 16) / 256, 2);   // (4096, 2)
    quant_both_kernel<<<qgrid, 256>>>((const float4*)x, (const float4*)w);
    quant_bias_kernel<<<NDIM / 256, 256>>>(b);

    // build tensormaps (host-side, pure; no allocation)
    void* encFn = nullptr;
    cudaDriverEntryPointQueryResult qres;
    cudaGetDriverEntryPoint("cuTensorMapEncodeTiled", &encFn, cudaEnableDefault, &qres);
    PFN_tmEncode enc = (PFN_tmEncode)encFn;

    void *xq_ptr = nullptr, *wq_ptr = nullptr;
    cudaGetSymbolAddress(&xq_ptr, g_Xq);
    cudaGetSymbolAddress(&wq_ptr, g_Wq);

    cuuint64_t dims[2]    = {(cuuint64_t)NDIM, (cuuint64_t)NDIM};
    cuuint64_t strides[1] = {(cuuint64_t)NDIM * 2};
    cuuint32_t box[2]     = {(cuuint32_t)BK, (cuuint32_t)BM};   // 64 elems x 128 rows
    cuuint32_t estr[2]    = {1, 1};

    CUtensorMap tmA, tmB;
    enc(&tmA, CU_TENSOR_MAP_DATA_TYPE_BFLOAT16, 2, xq_ptr, dims, strides, box, estr,
        CU_TENSOR_MAP_INTERLEAVE_NONE, CU_TENSOR_MAP_SWIZZLE_128B,
        CU_TENSOR_MAP_L2_PROMOTION_L2_128B, CU_TENSOR_MAP_FLOAT_OOB_FILL_NONE);
    enc(&tmB, CU_TENSOR_MAP_DATA_TYPE_BFLOAT16, 2, wq_ptr, dims, strides, box, estr,
        CU_TENSOR_MAP_INTERLEAVE_NONE, CU_TENSOR_MAP_SWIZZLE_128B,
        CU_TENSOR_MAP_L2_PROMOTION_L2_128B, CU_TENSOR_MAP_FLOAT_OOB_FILL_NONE);

    cudaFuncSetAttribute(gemm_kernel, cudaFuncAttributeMaxDynamicSharedMemorySize, SMEM_TOTAL);
    dim3 grid(NDIM / BN, NDIM / BM);            // 32 x 32 = 1024 CTAs
    gemm_kernel<<<grid, 288, SMEM_TOTAL>>>(tmA, tmB, nz, out);
}